// round 1
// baseline (speedup 1.0000x reference)
#include <cuda_runtime.h>

#define NB 2
#define CD 256
#define NT 16384
#define INNER_C 1024
#define NHEAD 16

// ---------------- scratch (static device globals; no allocation) ----------------
__device__ float d_xn[NB*CD*NT];          // x transposed to NCHW  (33.5 MB)
__device__ float d_q[NB*INNER_C*NT];      // q conv out, later reused as xo (134 MB)
__device__ float d_k[NB*INNER_C*NT];
__device__ float d_v[NB*INNER_C*NT];
__device__ float d_qpart[NB*INNER_C*64];
__device__ float d_kpart[NB*INNER_C*64];
__device__ float d_rnq[NB*INNER_C];
__device__ float d_rnk[NB*INNER_C];
__device__ float d_part[NB*NHEAD*32*64*64];  // attn partials (16.8 MB)
__device__ float d_attn[NB*NHEAD*64*64];
__device__ float d_p1[NB*CD*NT];          // vp (NCHW)
__device__ float d_g[NB*CD*NT];           // gelu(conv1(vp))
__device__ float d_pe[NB*CD*NT];          // conv2 output

// ---------------- NHWC -> NCHW transpose ----------------
__global__ void transpose_x_kernel(const float* __restrict__ x_in){
  __shared__ float tile[32][33];
  int b = blockIdx.z;
  int n0 = blockIdx.x*32, c0 = blockIdx.y*32;
  int tx = threadIdx.x, ty = threadIdx.y;
  tile[ty][tx] = x_in[((long)b*NT + n0+ty)*CD + c0+tx];
  __syncthreads();
  d_xn[((long)b*CD + c0+ty)*NT + n0+tx] = tile[tx][ty];
}

// ---------------- fused dwconv(3x3, groups=256, 4 out/ch) + BN for q,k,v ----------------
__global__ void __launch_bounds__(256) conv_qkv_kernel(
    const float* __restrict__ wq, const float* __restrict__ wk, const float* __restrict__ wv,
    const float* __restrict__ gq, const float* __restrict__ bq, const float* __restrict__ mq, const float* __restrict__ vq,
    const float* __restrict__ gk, const float* __restrict__ bk, const float* __restrict__ mk, const float* __restrict__ vk,
    const float* __restrict__ gv, const float* __restrict__ bv, const float* __restrict__ mv, const float* __restrict__ vv)
{
  int b = blockIdx.z, oc = blockIdx.y;
  int tid = threadIdx.x;
  int nn = blockIdx.x*256 + tid;
  int hh = nn >> 7, ww = nn & 127;
  int ci = oc >> 2;
  const float* xp = d_xn + ((long)b*CD + ci)*NT;
  float wr0[9], wr1[9], wr2[9];
  #pragma unroll
  for (int i=0;i<9;i++){ wr0[i]=__ldg(&wq[oc*9+i]); wr1[i]=__ldg(&wk[oc*9+i]); wr2[i]=__ldg(&wv[oc*9+i]); }
  float sq=0.f, sk=0.f, sv=0.f;
  #pragma unroll
  for (int dy=0; dy<3; dy++){
    int y = hh+dy-1;
    if ((unsigned)y < 128u){
      #pragma unroll
      for (int dx=0; dx<3; dx++){
        int xx = ww+dx-1;
        if ((unsigned)xx < 128u){
          float xv = xp[y*128+xx];
          sq = fmaf(xv, wr0[dy*3+dx], sq);
          sk = fmaf(xv, wr1[dy*3+dx], sk);
          sv = fmaf(xv, wr2[dy*3+dx], sv);
        }
      }
    }
  }
  float yq = (sq - mq[oc]) * (gq[oc]*rsqrtf(vq[oc]+1e-5f)) + bq[oc];
  float yk = (sk - mk[oc]) * (gk[oc]*rsqrtf(vk[oc]+1e-5f)) + bk[oc];
  float yv = (sv - mv[oc]) * (gv[oc]*rsqrtf(vv[oc]+1e-5f)) + bv[oc];
  long o = ((long)b*INNER_C + oc)*NT + nn;
  d_q[o]=yq; d_k[o]=yk; d_v[o]=yv;
  // block-reduce sum of squares (deterministic: per-block partials)
  __shared__ float rq[256], rk2[256];
  rq[tid]=yq*yq; rk2[tid]=yk*yk;
  __syncthreads();
  for (int s=128;s>0;s>>=1){
    if (tid<s){ rq[tid]+=rq[tid+s]; rk2[tid]+=rk2[tid+s]; }
    __syncthreads();
  }
  if (tid==0){
    d_qpart[((long)b*INNER_C+oc)*64 + blockIdx.x] = rq[0];
    d_kpart[((long)b*INNER_C+oc)*64 + blockIdx.x] = rk2[0];
  }
}

// ---------------- finalize L2 row norms ----------------
__global__ void norms_kernel(){
  int idx = blockIdx.x*256 + threadIdx.x; // 0..2047
  float sq=0.f, sk=0.f;
  #pragma unroll 8
  for (int c=0;c<64;c++){ sq += d_qpart[(long)idx*64+c]; sk += d_kpart[(long)idx*64+c]; }
  d_rnq[idx] = 1.f/fmaxf(sqrtf(sq),1e-12f);
  d_rnk[idx] = 1.f/fmaxf(sqrtf(sk),1e-12f);
}

// ---------------- attn logits partials: P[d,e] = sum_n k[d,n]*q[e,n] over 512-token chunks ----------------
__global__ void __launch_bounds__(256) attn_partial_kernel(){
  int b=blockIdx.z, h=blockIdx.y, ch=blockIdx.x;
  int tid = threadIdx.x;
  int n0 = ch*512;
  __shared__ float ks[64][33];
  __shared__ float qs[64][33];
  int d0 = (tid>>4)*4, e0=(tid&15)*4;
  float acc[4][4];
  #pragma unroll
  for (int i=0;i<4;i++)
    #pragma unroll
    for(int j=0;j<4;j++) acc[i][j]=0.f;
  const float* kb = d_k + ((long)b*INNER_C + h*64)*NT;
  const float* qb = d_q + ((long)b*INNER_C + h*64)*NT;
  for (int s=0;s<16;s++){
    int nb = n0 + s*32;
    __syncthreads();
    #pragma unroll
    for (int l=0;l<8;l++){
      int idx = l*256 + tid;
      int row = idx>>5, col = idx&31;
      ks[row][col] = kb[(long)row*NT + nb + col];
      qs[row][col] = qb[(long)row*NT + nb + col];
    }
    __syncthreads();
    #pragma unroll
    for (int t=0;t<32;t++){
      float ka[4], qa[4];
      #pragma unroll
      for (int i=0;i<4;i++){ ka[i]=ks[d0+i][t]; qa[i]=qs[e0+i][t]; }
      #pragma unroll
      for (int i=0;i<4;i++)
        #pragma unroll
        for (int j=0;j<4;j++)
          acc[i][j] = fmaf(ka[i], qa[j], acc[i][j]);
    }
  }
  float* pp = d_part + (((long)(b*NHEAD+h)*32 + ch)*4096);
  #pragma unroll
  for (int i=0;i<4;i++)
    #pragma unroll
    for (int j=0;j<4;j++)
      pp[(d0+i)*64 + e0+j] = acc[i][j];
}

// ---------------- reduce partials, apply norms + rescale, softmax over e ----------------
__global__ void softmax_kernel(const float* __restrict__ rescale){
  int h = blockIdx.x, b = blockIdx.y;
  int d = threadIdx.x; // 64 threads
  float acc[64];
  #pragma unroll
  for (int e=0;e<64;e++) acc[e]=0.f;
  const float* base = d_part + ((long)(b*NHEAD+h)*32)*4096 + d*64;
  for (int ch=0; ch<32; ch++){
    const float* p = base + (long)ch*4096;
    #pragma unroll
    for (int e=0;e<64;e++) acc[e] += p[e];
  }
  float sc = rescale[h]*d_rnk[b*INNER_C + h*64 + d];
  const float* rq = &d_rnq[b*INNER_C + h*64];
  float m = -1e30f;
  #pragma unroll
  for (int e=0;e<64;e++){ acc[e] = acc[e]*sc*rq[e]; m = fmaxf(m, acc[e]); }
  float s = 0.f;
  #pragma unroll
  for (int e=0;e<64;e++){ acc[e] = expf(acc[e]-m); s += acc[e]; }
  float inv = 1.f/s;
  float* ap = d_attn + ((long)(b*NHEAD+h)*64 + d)*64;
  #pragma unroll
  for (int e=0;e<64;e++) ap[e] = acc[e]*inv;
}

// ---------------- xo = attn @ v  (writes into d_q, which is free after softmax) ----------------
__global__ void __launch_bounds__(256) xo_kernel(){
  int b=blockIdx.z, h=blockIdx.y;
  int t0 = blockIdx.x*64;
  int tid = threadIdx.x;
  __shared__ float as_[64][65];   // attn [d][e]
  __shared__ float vs[16][68];    // v chunk [e'][t]
  const float* ap = d_attn + (long)(b*NHEAD+h)*4096;
  #pragma unroll
  for (int l=0;l<16;l++){
    int idx = l*256+tid;
    as_[idx>>6][idx&63] = ap[idx];
  }
  int ty = tid>>4, tx = tid&15;
  int dd0 = ty*4, tt0 = tx*4;
  const float* vb = d_v + ((long)b*INNER_C + h*64)*NT + t0;
  float acc[4][4];
  #pragma unroll
  for (int i=0;i<4;i++)
    #pragma unroll
    for(int j=0;j<4;j++) acc[i][j]=0.f;
  for (int ec=0; ec<4; ec++){
    __syncthreads();
    {
      int r = tid>>4;
      int c = (tid&15)*4;
      float4 vv = *(const float4*)&vb[(long)(ec*16 + r)*NT + c];
      vs[r][c]=vv.x; vs[r][c+1]=vv.y; vs[r][c+2]=vv.z; vs[r][c+3]=vv.w;
    }
    __syncthreads();
    #pragma unroll
    for (int e=0;e<16;e++){
      float a4[4], b4[4];
      #pragma unroll
      for (int i=0;i<4;i++){ a4[i]=as_[dd0+i][ec*16+e]; b4[i]=vs[e][tt0+i]; }
      #pragma unroll
      for (int i=0;i<4;i++)
        #pragma unroll
        for (int j=0;j<4;j++)
          acc[i][j] = fmaf(a4[i], b4[j], acc[i][j]);
    }
  }
  #pragma unroll
  for (int i=0;i<4;i++){
    float4 w; w.x=acc[i][0]; w.y=acc[i][1]; w.z=acc[i][2]; w.w=acc[i][3];
    *(float4*)&d_q[((long)b*INNER_C + h*64 + dd0+i)*NT + t0 + tt0] = w;
  }
}

// ---------------- GEMM1: vp[b,co,nn] = sum_k W[co,k]*V[b,k,nn] + bias[co]  (128x128x8, 8x8/thr) ----------------
__global__ void __launch_bounds__(256) gemm_vp_kernel(const float* __restrict__ W, const float* __restrict__ bias){
  int b = blockIdx.z;
  int n0 = blockIdx.x*128;
  int m0 = blockIdx.y*128;
  __shared__ float As[8][128];
  __shared__ float Bs[8][128];
  int tid = threadIdx.x;
  int tx = tid&15, ty=tid>>4;
  int mr = ty*8, nc = tx*8;
  const float* Vb = d_v + (long)b*INNER_C*NT;
  int a_m = tid>>1, a_k = (tid&1)*4;
  int b_k = tid>>5, b_n = (tid&31)*4;
  float acc[8][8];
  #pragma unroll
  for (int i=0;i<8;i++)
    #pragma unroll
    for (int j=0;j<8;j++) acc[i][j]=0.f;
  for (int k0=0;k0<1024;k0+=8){
    float4 av  = *(const float4*)&W[(m0+a_m)*1024 + k0 + a_k];
    float4 bv2 = *(const float4*)&Vb[(long)(k0+b_k)*NT + n0 + b_n];
    __syncthreads();
    As[a_k+0][a_m]=av.x; As[a_k+1][a_m]=av.y; As[a_k+2][a_m]=av.z; As[a_k+3][a_m]=av.w;
    *(float4*)&Bs[b_k][b_n] = bv2;
    __syncthreads();
    #pragma unroll
    for (int kk=0;kk<8;kk++){
      float ar[8], br[8];
      *(float4*)&ar[0] = *(const float4*)&As[kk][mr];
      *(float4*)&ar[4] = *(const float4*)&As[kk][mr+4];
      *(float4*)&br[0] = *(const float4*)&Bs[kk][nc];
      *(float4*)&br[4] = *(const float4*)&Bs[kk][nc+4];
      #pragma unroll
      for (int i=0;i<8;i++)
        #pragma unroll
        for (int j=0;j<8;j++)
          acc[i][j] = fmaf(ar[i], br[j], acc[i][j]);
    }
  }
  #pragma unroll
  for (int i=0;i<8;i++){
    float bi = bias[m0+mr+i];
    float* cp = d_p1 + ((long)b*CD + m0+mr+i)*NT + n0 + nc;
    float4 w0, w1;
    w0.x=acc[i][0]+bi; w0.y=acc[i][1]+bi; w0.z=acc[i][2]+bi; w0.w=acc[i][3]+bi;
    w1.x=acc[i][4]+bi; w1.y=acc[i][5]+bi; w1.z=acc[i][6]+bi; w1.w=acc[i][7]+bi;
    *(float4*)&cp[0]=w0; *(float4*)&cp[4]=w1;
  }
}

// ---------------- GEMM2: out[b,r,co] = sum_k XO[b,r,k]*W[co,k] + bias[co] ----------------
__global__ void __launch_bounds__(256) gemm_out_kernel(const float* __restrict__ W, const float* __restrict__ bias,
                                                       float* __restrict__ out){
  int b = blockIdx.z;
  int n0 = blockIdx.x*128; // co
  int m0 = blockIdx.y*128; // r
  __shared__ float As[8][128];
  __shared__ float Bs[8][128];
  int tid=threadIdx.x, tx=tid&15, ty=tid>>4;
  int mr=ty*8, nc=tx*8;
  const float* A = d_q + (long)b*INNER_C*NT; // xo, flat-reshaped [16384,1024]
  int lm = tid>>1, lk = (tid&1)*4;
  float acc[8][8];
  #pragma unroll
  for (int i=0;i<8;i++)
    #pragma unroll
    for (int j=0;j<8;j++) acc[i][j]=0.f;
  for (int k0=0;k0<1024;k0+=8){
    float4 av  = *(const float4*)&A[(long)(m0+lm)*1024 + k0+lk];
    float4 bv2 = *(const float4*)&W[(n0+lm)*1024 + k0+lk];
    __syncthreads();
    As[lk+0][lm]=av.x;  As[lk+1][lm]=av.y;  As[lk+2][lm]=av.z;  As[lk+3][lm]=av.w;
    Bs[lk+0][lm]=bv2.x; Bs[lk+1][lm]=bv2.y; Bs[lk+2][lm]=bv2.z; Bs[lk+3][lm]=bv2.w;
    __syncthreads();
    #pragma unroll
    for (int kk=0;kk<8;kk++){
      float ar[8], br[8];
      *(float4*)&ar[0] = *(const float4*)&As[kk][mr];
      *(float4*)&ar[4] = *(const float4*)&As[kk][mr+4];
      *(float4*)&br[0] = *(const float4*)&Bs[kk][nc];
      *(float4*)&br[4] = *(const float4*)&Bs[kk][nc+4];
      #pragma unroll
      for (int i=0;i<8;i++)
        #pragma unroll
        for (int j=0;j<8;j++)
          acc[i][j] = fmaf(ar[i], br[j], acc[i][j]);
    }
  }
  #pragma unroll
  for (int i=0;i<8;i++){
    float* cp = out + ((long)b*NT + m0+mr+i)*CD + n0+nc;
    float4 w0, w1;
    w0.x=acc[i][0]+bias[n0+nc+0]; w0.y=acc[i][1]+bias[n0+nc+1];
    w0.z=acc[i][2]+bias[n0+nc+2]; w0.w=acc[i][3]+bias[n0+nc+3];
    w1.x=acc[i][4]+bias[n0+nc+4]; w1.y=acc[i][5]+bias[n0+nc+5];
    w1.z=acc[i][6]+bias[n0+nc+6]; w1.w=acc[i][7]+bias[n0+nc+7];
    *(float4*)&cp[0]=w0; *(float4*)&cp[4]=w1;
  }
}

// ---------------- positional path depthwise convs (stage0: conv1+GELU, stage1: conv2) ----------------
__global__ void __launch_bounds__(256) conv_pos_kernel(const float* __restrict__ w, int stage){
  const float* src = (stage==0) ? d_p1 : d_g;
  float* dst = (stage==0) ? d_g : d_pe;
  int b=blockIdx.z, c=blockIdx.y;
  int nn = blockIdx.x*256 + threadIdx.x;
  int hh=nn>>7, ww=nn&127;
  const float* xp = src + ((long)b*CD + c)*NT;
  float wr[9];
  #pragma unroll
  for (int i=0;i<9;i++) wr[i]=__ldg(&w[c*9+i]);
  float s=0.f;
  #pragma unroll
  for (int dy=0; dy<3; dy++){
    int y = hh+dy-1;
    if ((unsigned)y < 128u){
      #pragma unroll
      for (int dx=0; dx<3; dx++){
        int xx = ww+dx-1;
        if ((unsigned)xx < 128u)
          s = fmaf(xp[y*128+xx], wr[dy*3+dx], s);
      }
    }
  }
  if (stage==0) s = 0.5f*s*(1.f+erff(s*0.70710678118654752f));
  dst[((long)b*CD+c)*NT+nn]=s;
}

// ---------------- final: out += pe (NCHW -> NHWC transpose-add) ----------------
__global__ void final_add_kernel(float* __restrict__ out){
  __shared__ float tile[32][33];
  int b=blockIdx.z;
  int n0=blockIdx.x*32, c0=blockIdx.y*32;
  int tx=threadIdx.x, ty=threadIdx.y;
  tile[ty][tx] = d_pe[((long)b*CD + c0+ty)*NT + n0+tx];
  __syncthreads();
  long o = ((long)b*NT + n0+ty)*CD + c0+tx;
  out[o] = out[o] + tile[tx][ty];
}

extern "C" void kernel_launch(void* const* d_in, const int* in_sizes, int n_in,
                              void* d_out, int out_size) {
  const float* x_in  = (const float*)d_in[0];
  const float* wq    = (const float*)d_in[1];
  const float* wk    = (const float*)d_in[2];
  const float* wv    = (const float*)d_in[3];
  const float* bnq_g = (const float*)d_in[4];
  const float* bnq_b = (const float*)d_in[5];
  const float* bnq_m = (const float*)d_in[6];
  const float* bnq_v = (const float*)d_in[7];
  const float* bnk_g = (const float*)d_in[8];
  const float* bnk_b = (const float*)d_in[9];
  const float* bnk_m = (const float*)d_in[10];
  const float* bnk_v = (const float*)d_in[11];
  const float* bnv_g = (const float*)d_in[12];
  const float* bnv_b = (const float*)d_in[13];
  const float* bnv_m = (const float*)d_in[14];
  const float* bnv_v = (const float*)d_in[15];
  const float* rescale = (const float*)d_in[16];
  const float* proj_w  = (const float*)d_in[17];
  const float* proj_b  = (const float*)d_in[18];
  const float* pos_w1  = (const float*)d_in[19];
  const float* pos_w2  = (const float*)d_in[20];
  float* out = (float*)d_out;

  transpose_x_kernel<<<dim3(NT/32, CD/32, NB), dim3(32,32)>>>(x_in);
  conv_qkv_kernel<<<dim3(NT/256, INNER_C, NB), 256>>>(
      wq, wk, wv,
      bnq_g, bnq_b, bnq_m, bnq_v,
      bnk_g, bnk_b, bnk_m, bnk_v,
      bnv_g, bnv_b, bnv_m, bnv_v);
  norms_kernel<<<8, 256>>>();
  attn_partial_kernel<<<dim3(32, NHEAD, NB), 256>>>();
  softmax_kernel<<<dim3(NHEAD, NB), 64>>>(rescale);
  xo_kernel<<<dim3(NT/64, NHEAD, NB), 256>>>();
  gemm_vp_kernel<<<dim3(NT/128, CD/128, NB), 256>>>(proj_w, proj_b);
  conv_pos_kernel<<<dim3(NT/256, CD, NB), 256>>>(pos_w1, 0);
  conv_pos_kernel<<<dim3(NT/256, CD, NB), 256>>>(pos_w2, 1);
  gemm_out_kernel<<<dim3(CD/128, NT/128, NB), 256>>>(proj_w, proj_b, out);
  final_add_kernel<<<dim3(NT/32, CD/32, NB), dim3(32,32)>>>(out);
}